// round 1
// baseline (speedup 1.0000x reference)
#include <cuda_runtime.h>
#include <math.h>

// LSTM cell, B=4096, IN=H=1024.
//   hx = [x, h]  (4096 x 2048)
//   pre_g = hx @ W_g   (g in {forget, ignore, select, predict}), each 4096x1024
//   f=sig(pre_f+bf), i=sig(pre_i+bi), s=sig(pre_s+bs), p=tanh(pre_p+bp)
//   c_new = c*f + i*p ;  out = tanh(c_new)*s
//
// Round 0: exact-fp32 tiled SGEMM (128x128x16, 256 thr, 2x2 of 4x4 microtiles)
// writing pre-activations to static scratch, then a fused float4 eltwise
// epilogue. Compute-bound baseline; tensor-core (tf32 tcgen05) port comes next.

#define BM 128
#define BN 128
#define BK 16

static __device__ float g_pre[4ull * 4096ull * 1024ull];  // 64 MB scratch

__global__ __launch_bounds__(256, 2)
void gemm4_kernel(const float* __restrict__ x, const float* __restrict__ h,
                  const float* __restrict__ Wf, const float* __restrict__ Wi,
                  const float* __restrict__ Ws, const float* __restrict__ Wp) {
    __shared__ float As[BK][BM];   // [k][m]
    __shared__ float Bs[BK][BN];   // [k][n]

    const int m0    = blockIdx.y * BM;          // row tile (batch)
    const int nglob = blockIdx.x * BN;          // global gate-column 0..4095
    const int gate  = nglob >> 10;              // 128 | 1024 -> single gate/block
    const int col0  = nglob & 1023;

    const float* __restrict__ W =
        (gate == 0) ? Wf : (gate == 1) ? Wi : (gate == 2) ? Ws : Wp;
    float* __restrict__ out = g_pre + (size_t)gate * (4096ull * 1024ull);

    const int tid = threadIdx.x;
    // A-tile loader: 128 rows x 16 cols; thread -> (row, 4-col group), 2 iters
    const int a_r = tid >> 2;            // 0..63
    const int a_c = (tid & 3) * 4;       // 0,4,8,12
    // B-tile loader: 16 rows x 128 cols; thread -> (row, 4-col group), 2 iters
    const int b_r = tid >> 5;            // 0..7
    const int b_c = (tid & 31) * 4;      // 0..124

    const int tx = tid & 15;             // n-fragment id
    const int ty = tid >> 4;             // m-fragment id

    float acc[2][2][4][4];
    #pragma unroll
    for (int ih = 0; ih < 2; ++ih)
        #pragma unroll
        for (int jh = 0; jh < 2; ++jh)
            #pragma unroll
            for (int i = 0; i < 4; ++i)
                #pragma unroll
                for (int j = 0; j < 4; ++j)
                    acc[ih][jh][i][j] = 0.0f;

    // K = 2048 = 128 k-tiles of 16. Tiles 0..63 read x, 64..127 read h
    // (16 | 1024, so a tile never straddles the concat boundary).
    for (int kt = 0; kt < 128; ++kt) {
        const float* __restrict__ Ab = (kt < 64) ? x : h;
        const int kk = (kt & 63) * BK;

        #pragma unroll
        for (int it = 0; it < 2; ++it) {
            const int r = a_r + it * 64;
            float4 v = *(const float4*)&Ab[(size_t)(m0 + r) * 1024 + kk + a_c];
            As[a_c + 0][r] = v.x;
            As[a_c + 1][r] = v.y;
            As[a_c + 2][r] = v.z;
            As[a_c + 3][r] = v.w;
        }
        #pragma unroll
        for (int it = 0; it < 2; ++it) {
            const int r = b_r + it * 8;
            *(float4*)&Bs[r][b_c] =
                *(const float4*)&W[(size_t)(kt * BK + r) * 1024 + col0 + b_c];
        }
        __syncthreads();

        #pragma unroll
        for (int k = 0; k < BK; ++k) {
            // Conflict-free fragment layout: halves at 0 and 64.
            float4 a0 = *(const float4*)&As[k][ty * 4];
            float4 a1 = *(const float4*)&As[k][64 + ty * 4];
            float4 b0 = *(const float4*)&Bs[k][tx * 4];
            float4 b1 = *(const float4*)&Bs[k][64 + tx * 4];
            float av[2][4] = {{a0.x, a0.y, a0.z, a0.w}, {a1.x, a1.y, a1.z, a1.w}};
            float bv[2][4] = {{b0.x, b0.y, b0.z, b0.w}, {b1.x, b1.y, b1.z, b1.w}};
            #pragma unroll
            for (int ih = 0; ih < 2; ++ih)
                #pragma unroll
                for (int i = 0; i < 4; ++i)
                    #pragma unroll
                    for (int jh = 0; jh < 2; ++jh)
                        #pragma unroll
                        for (int j = 0; j < 4; ++j)
                            acc[ih][jh][i][j] = fmaf(av[ih][i], bv[jh][j],
                                                     acc[ih][jh][i][j]);
        }
        __syncthreads();
    }

    #pragma unroll
    for (int ih = 0; ih < 2; ++ih) {
        #pragma unroll
        for (int i = 0; i < 4; ++i) {
            const int row = m0 + ih * 64 + ty * 4 + i;
            #pragma unroll
            for (int jh = 0; jh < 2; ++jh) {
                const int col = col0 + jh * 64 + tx * 4;
                float4 v = make_float4(acc[ih][jh][i][0], acc[ih][jh][i][1],
                                       acc[ih][jh][i][2], acc[ih][jh][i][3]);
                *(float4*)&out[(size_t)row * 1024 + col] = v;
            }
        }
    }
}

__device__ __forceinline__ float sigf(float z) {
    return 1.0f / (1.0f + expf(-z));
}

__global__ __launch_bounds__(256)
void lstm_eltwise_kernel(const float* __restrict__ c,
                         const float* __restrict__ bf, const float* __restrict__ bi,
                         const float* __restrict__ bs, const float* __restrict__ bp,
                         float* __restrict__ out) {
    const size_t G = 4096ull * 1024ull;
    const size_t i4 = (size_t)blockIdx.x * blockDim.x + threadIdx.x;  // < 1048576
    const size_t idx = i4 * 4;
    const int col = (int)(idx & 1023);

    float4 pf = *(const float4*)&g_pre[idx];
    float4 pi = *(const float4*)&g_pre[G + idx];
    float4 ps = *(const float4*)&g_pre[2 * G + idx];
    float4 pp = *(const float4*)&g_pre[3 * G + idx];
    float4 vbf = *(const float4*)&bf[col];
    float4 vbi = *(const float4*)&bi[col];
    float4 vbs = *(const float4*)&bs[col];
    float4 vbp = *(const float4*)&bp[col];
    float4 vc  = *(const float4*)&c[idx];

    const float* pfv = (const float*)&pf;
    const float* piv = (const float*)&pi;
    const float* psv = (const float*)&ps;
    const float* ppv = (const float*)&pp;
    const float* bfv = (const float*)&vbf;
    const float* biv = (const float*)&vbi;
    const float* bsv = (const float*)&vbs;
    const float* bpv = (const float*)&vbp;
    const float* cv  = (const float*)&vc;

    float4 o;
    float* ov = (float*)&o;
    #pragma unroll
    for (int j = 0; j < 4; ++j) {
        float f = sigf(pfv[j] + bfv[j]);
        float i = sigf(piv[j] + biv[j]);
        float s = sigf(psv[j] + bsv[j]);
        float p = tanhf(ppv[j] + bpv[j]);
        float cn = cv[j] * f + i * p;
        ov[j] = tanhf(cn) * s;
    }
    *(float4*)&out[idx] = o;
}

extern "C" void kernel_launch(void* const* d_in, const int* in_sizes, int n_in,
                              void* d_out, int out_size) {
    const float* x  = (const float*)d_in[0];
    const float* h  = (const float*)d_in[1];
    const float* c  = (const float*)d_in[2];
    const float* Wf = (const float*)d_in[3];
    const float* bf = (const float*)d_in[4];
    const float* Wi = (const float*)d_in[5];
    const float* bi = (const float*)d_in[6];
    const float* Ws = (const float*)d_in[7];
    const float* bs = (const float*)d_in[8];
    const float* Wp = (const float*)d_in[9];
    const float* bp = (const float*)d_in[10];
    float* out = (float*)d_out;

    dim3 grid(4096 / BN * 4 / 4 * 4, 4096 / BM);  // (32, 32)
    gemm4_kernel<<<dim3(32, 32), 256>>>(x, h, Wf, Wi, Ws, Wp);
    lstm_eltwise_kernel<<<4096, 256>>>(c, bf, bi, bs, bp, out);
}

// round 3
// speedup vs baseline: 1.9117x; 1.9117x over previous
#include <cuda_runtime.h>
#include <cuda_bf16.h>
#include <math.h>
#include <stdint.h>

// LSTM cell B=4096, IN=H=1024.
// bf16x3 GEMM on tensor cores via baseline-PTX mma.sync (sm_100-safe):
//   A' = [hx_hi | hx_lo | hx_hi]   (4096 x 6144 bf16, K-major)
//   B' rows n=gate*1024+col hold [W_hi ; W_hi ; W_lo]^T  (4096 x 6144 bf16)
//   pre = A' @ B'^T  (fp32 accum)  ==  hx@W to ~1e-5 rel err.
// Then fused eltwise epilogue.

#define KE 6144
#define BM 128
#define BN 256
#define BK 64
#define KTILES 96                      // 6144/64
#define STAGES 3
#define A_STAGE_BYTES (BM * 128)       // 16384
#define B_STAGE_BYTES (BN * 128)       // 32768
#define STAGE_BYTES (A_STAGE_BYTES + B_STAGE_BYTES)
#define SMEM_DYN (STAGES * STAGE_BYTES)

static __device__ __align__(16) __nv_bfloat16 g_A[4096ull * KE];   // 48 MB
static __device__ __align__(16) __nv_bfloat16 g_B[4096ull * KE];   // 48 MB
static __device__ float g_pre[4ull * 4096ull * 1024ull];           // 64 MB

// ---------------- PTX helpers (all baseline sm_80 ISA) ----------------
__device__ __forceinline__ uint32_t smem_u32(const void* p) {
    return (uint32_t)__cvta_generic_to_shared(p);
}
__device__ __forceinline__ void cp16(uint32_t dst, const void* src) {
    asm volatile("cp.async.cg.shared.global [%0], [%1], 16;\n" :: "r"(dst), "l"(src));
}
__device__ __forceinline__ void cp_commit() {
    asm volatile("cp.async.commit_group;\n" ::: "memory");
}
#define CP_WAIT(N) asm volatile("cp.async.wait_group %0;\n" :: "n"(N) : "memory")

__device__ __forceinline__ void ldsm_x4(uint32_t* r, uint32_t addr) {
    asm volatile("ldmatrix.sync.aligned.m8n8.x4.shared.b16 {%0,%1,%2,%3}, [%4];\n"
                 : "=r"(r[0]), "=r"(r[1]), "=r"(r[2]), "=r"(r[3]) : "r"(addr));
}
__device__ __forceinline__ void mma16816(float* c, const uint32_t* a,
                                         uint32_t b0, uint32_t b1) {
    asm volatile(
        "mma.sync.aligned.m16n8k16.row.col.f32.bf16.bf16.f32 "
        "{%0,%1,%2,%3}, {%4,%5,%6,%7}, {%8,%9}, {%0,%1,%2,%3};\n"
        : "+f"(c[0]), "+f"(c[1]), "+f"(c[2]), "+f"(c[3])
        : "r"(a[0]), "r"(a[1]), "r"(a[2]), "r"(a[3]), "r"(b0), "r"(b1));
}

// ---------------- conversion kernels ----------------
__global__ __launch_bounds__(256)
void split_hx(const float* __restrict__ x, const float* __restrict__ h) {
    size_t g = (size_t)blockIdx.x * 256 + threadIdx.x;
    size_t idx = g * 4;                        // element index in [4096][2048]
    int m = (int)(idx >> 11);
    int j = (int)(idx & 2047);
    const float* src = (j < 1024) ? (x + (size_t)m * 1024 + j)
                                  : (h + (size_t)m * 1024 + (j - 1024));
    float4 v = *(const float4*)src;
    __nv_bfloat16 h0 = __float2bfloat16(v.x);
    __nv_bfloat16 h1 = __float2bfloat16(v.y);
    __nv_bfloat16 h2 = __float2bfloat16(v.z);
    __nv_bfloat16 h3 = __float2bfloat16(v.w);
    __nv_bfloat162 hi01; hi01.x = h0; hi01.y = h1;
    __nv_bfloat162 hi23; hi23.x = h2; hi23.y = h3;
    __nv_bfloat162 lo01; lo01.x = __float2bfloat16(v.x - __bfloat162float(h0));
                         lo01.y = __float2bfloat16(v.y - __bfloat162float(h1));
    __nv_bfloat162 lo23; lo23.x = __float2bfloat16(v.z - __bfloat162float(h2));
                         lo23.y = __float2bfloat16(v.w - __bfloat162float(h3));
    size_t base = (size_t)m * KE + j;
    *(__nv_bfloat162*)(g_A + base)        = hi01;
    *(__nv_bfloat162*)(g_A + base + 2)    = hi23;
    *(__nv_bfloat162*)(g_A + base + 2048) = lo01;
    *(__nv_bfloat162*)(g_A + base + 2050) = lo23;
    *(__nv_bfloat162*)(g_A + base + 4096) = hi01;
    *(__nv_bfloat162*)(g_A + base + 4098) = hi23;
}

__global__ __launch_bounds__(256)
void split_w(const float* __restrict__ Wf, const float* __restrict__ Wi,
             const float* __restrict__ Ws, const float* __restrict__ Wp) {
    __shared__ float t[32][33];
    int g = blockIdx.z;
    const float* __restrict__ W = (g == 0) ? Wf : (g == 1) ? Wi : (g == 2) ? Ws : Wp;
    int n0 = blockIdx.x * 32, k0 = blockIdx.y * 32;
    int tx = threadIdx.x & 31, ty = threadIdx.x >> 5;   // ty 0..7
    #pragma unroll
    for (int r = 0; r < 4; ++r)
        t[ty + r * 8][tx] = W[(size_t)(k0 + ty + r * 8) * 1024 + n0 + tx];
    __syncthreads();
    #pragma unroll
    for (int r = 0; r < 4; ++r) {
        int nl = ty + r * 8;
        float v = t[tx][nl];
        __nv_bfloat16 hi = __float2bfloat16(v);
        __nv_bfloat16 lo = __float2bfloat16(v - __bfloat162float(hi));
        size_t row = (size_t)(g * 1024 + n0 + nl) * KE;
        g_B[row + k0 + tx]        = hi;
        g_B[row + 2048 + k0 + tx] = hi;
        g_B[row + 4096 + k0 + tx] = lo;
    }
}

// ---------------- tensor-core GEMM (mma.sync) ----------------
__device__ __forceinline__ void load_stage(uint32_t sbase, int stage, int m0, int n0,
                                           int tid) {
    const uint32_t sb = sbase + (uint32_t)(stage % STAGES) * STAGE_BYTES;
    const int kcol = stage * BK;
    #pragma unroll
    for (int j = 0; j < 4; ++j) {              // A: 128 rows x 128B
        int id = j * 256 + tid;
        int r = id >> 3, c = id & 7;
        uint32_t dst = sb + (uint32_t)(r * 128 + ((c ^ (r & 7)) * 16));
        cp16(dst, g_A + ((size_t)(m0 + r) * KE + kcol + c * 8));
    }
    #pragma unroll
    for (int j = 0; j < 8; ++j) {              // B: 256 rows x 128B
        int id = j * 256 + tid;
        int r = id >> 3, c = id & 7;
        uint32_t dst = sb + (uint32_t)A_STAGE_BYTES
                     + (uint32_t)(r * 128 + ((c ^ (r & 7)) * 16));
        cp16(dst, g_B + ((size_t)(n0 + r) * KE + kcol + c * 8));
    }
}

__global__ __launch_bounds__(256, 1)
void gemm_mma() {
    extern __shared__ char dyn[];
    const uint32_t sbase = smem_u32(dyn);

    const int tid = threadIdx.x;
    const int wid = tid >> 5;
    const int lane = tid & 31;
    const int warp_m = wid & 1;                // 0..1 -> 64-row slab
    const int warp_n = wid >> 1;               // 0..3 -> 64-col slab
    const int m0 = blockIdx.y * BM;
    const int n0 = blockIdx.x * BN;

    // Per-thread ldmatrix row geometry (row within 8-group fixed per lane)
    const int lrow = lane & 15;                // row offset in 16-row tile
    const int lhi  = lane >> 4;                // 0/1 -> +8 elem (one chunk) in k

    float acc[4][8][4];
    #pragma unroll
    for (int mi = 0; mi < 4; ++mi)
        #pragma unroll
        for (int nj = 0; nj < 8; ++nj)
            #pragma unroll
            for (int q = 0; q < 4; ++q) acc[mi][nj][q] = 0.0f;

    // Prefetch stages 0,1
    load_stage(sbase, 0, m0, n0, tid); cp_commit();
    load_stage(sbase, 1, m0, n0, tid); cp_commit();

    for (int kt = 0; kt < KTILES; ++kt) {
        CP_WAIT(1);                 // stage kt resident
        __syncthreads();            // also guarantees stage kt-1 consumed by all

        if (kt + 2 < KTILES) load_stage(sbase, kt + 2, m0, n0, tid);
        cp_commit();

        const uint32_t sA = sbase + (uint32_t)(kt % STAGES) * STAGE_BYTES;
        const uint32_t sB = sA + A_STAGE_BYTES;

        #pragma unroll
        for (int ks = 0; ks < 4; ++ks) {       // 4 x k16 per 64-wide stage
            const int kc = ks * 2 + lhi;       // 16B-chunk index 0..7
            uint32_t a[4][4], b[4][4];
            #pragma unroll
            for (int mi = 0; mi < 4; ++mi) {
                int r = warp_m * 64 + mi * 16 + lrow;
                uint32_t addr = sA + (uint32_t)(r * 128 + ((kc ^ (r & 7)) * 16));
                ldsm_x4(a[mi], addr);
            }
            #pragma unroll
            for (int nj = 0; nj < 4; ++nj) {
                int r = warp_n * 64 + nj * 16 + lrow;
                uint32_t addr = sB + (uint32_t)(r * 128 + ((kc ^ (r & 7)) * 16));
                ldsm_x4(b[nj], addr);
            }
            #pragma unroll
            for (int mi = 0; mi < 4; ++mi)
                #pragma unroll
                for (int nj = 0; nj < 4; ++nj) {
                    mma16816(acc[mi][2 * nj],     a[mi], b[nj][0], b[nj][2]);
                    mma16816(acc[mi][2 * nj + 1], a[mi], b[nj][1], b[nj][3]);
                }
        }
    }

    // Epilogue: warp owns 64x64 at (m0+warp_m*64, n0+warp_n*64)
    const int gid = lane >> 2, tig = lane & 3;
    const int ng = n0 + warp_n * 64;
    const int gate = ng >> 10;
    const int col0 = ng & 1023;
    float* __restrict__ outg = g_pre + (size_t)gate * (4096ull * 1024ull);
    #pragma unroll
    for (int mi = 0; mi < 4; ++mi) {
        int row = m0 + warp_m * 64 + mi * 16 + gid;
        float* p0 = outg + (size_t)row * 1024 + col0;
        float* p1 = p0 + 8ull * 1024ull;
        #pragma unroll
        for (int nj = 0; nj < 8; ++nj) {
            int col = nj * 8 + tig * 2;
            *(float2*)(p0 + col) = make_float2(acc[mi][nj][0], acc[mi][nj][1]);
            *(float2*)(p1 + col) = make_float2(acc[mi][nj][2], acc[mi][nj][3]);
        }
    }
}

// ---------------- fused eltwise ----------------
__device__ __forceinline__ float sigf(float z) { return 1.0f / (1.0f + expf(-z)); }

__global__ __launch_bounds__(256)
void lstm_eltwise_kernel(const float* __restrict__ c,
                         const float* __restrict__ bf, const float* __restrict__ bi,
                         const float* __restrict__ bs, const float* __restrict__ bp,
                         float* __restrict__ out) {
    const size_t G = 4096ull * 1024ull;
    const size_t i4 = (size_t)blockIdx.x * blockDim.x + threadIdx.x;
    const size_t idx = i4 * 4;
    const int col = (int)(idx & 1023);

    float4 pf = *(const float4*)&g_pre[idx];
    float4 pi = *(const float4*)&g_pre[G + idx];
    float4 ps = *(const float4*)&g_pre[2 * G + idx];
    float4 pp = *(const float4*)&g_pre[3 * G + idx];
    float4 vbf = *(const float4*)&bf[col];
    float4 vbi = *(const float4*)&bi[col];
    float4 vbs = *(const float4*)&bs[col];
    float4 vbp = *(const float4*)&bp[col];
    float4 vc  = *(const float4*)&c[idx];

    const float* pfv = (const float*)&pf;  const float* piv = (const float*)&pi;
    const float* psv = (const float*)&ps;  const float* ppv = (const float*)&pp;
    const float* bfv = (const float*)&vbf; const float* biv = (const float*)&vbi;
    const float* bsv = (const float*)&vbs; const float* bpv = (const float*)&vbp;
    const float* cv  = (const float*)&vc;

    float4 o; float* ov = (float*)&o;
    #pragma unroll
    for (int j = 0; j < 4; ++j) {
        float f = sigf(pfv[j] + bfv[j]);
        float i = sigf(piv[j] + biv[j]);
        float s = sigf(psv[j] + bsv[j]);
        float p = tanhf(ppv[j] + bpv[j]);
        float cn = cv[j] * f + i * p;
        ov[j] = tanhf(cn) * s;
    }
    *(float4*)&out[idx] = o;
}

// ---------------- launch ----------------
extern "C" void kernel_launch(void* const* d_in, const int* in_sizes, int n_in,
                              void* d_out, int out_size) {
    const float* x  = (const float*)d_in[0];
    const float* h  = (const float*)d_in[1];
    const float* c  = (const float*)d_in[2];
    const float* Wf = (const float*)d_in[3];
    const float* bf = (const float*)d_in[4];
    const float* Wi = (const float*)d_in[5];
    const float* bi = (const float*)d_in[6];
    const float* Ws = (const float*)d_in[7];
    const float* bs = (const float*)d_in[8];
    const float* Wp = (const float*)d_in[9];
    const float* bp = (const float*)d_in[10];
    float* out = (float*)d_out;

    cudaFuncSetAttribute(gemm_mma, cudaFuncAttributeMaxDynamicSharedMemorySize,
                         SMEM_DYN);

    split_hx<<<8192, 256>>>(x, h);
    split_w<<<dim3(32, 64, 4), 256>>>(Wf, Wi, Ws, Wp);
    gemm_mma<<<dim3(4096 / BN, 4096 / BM), 256, SMEM_DYN>>>();
    lstm_eltwise_kernel<<<4096, 256>>>(c, bf, bi, bs, bp, out);
}

// round 4
// speedup vs baseline: 3.3391x; 1.7466x over previous
#include <cuda_runtime.h>
#include <math.h>
#include <stdint.h>

// LSTM cell B=4096, IN=H=1024 — int8 Ozaki-split GEMM on IMMA m16n8k32.
//   hx[m,k] ≈ sa_m/16256 · (128·A1 + A2),  W col n: sb_n/16256 · (128·B1 + B2)
//   pre[m,n] = sa·sb/16256^2 · (16384·A1B1 + 128·(A1B2 + A2B1))   (A2B2 dropped)
// One GEMM, K''=6144: ktiles 0-15 A1·B1, then acc<<=7, 16-31 A2·B1, 32-47 A1·B2.
// s32 accumulation is exact; only quantization (~1e-4 rel) remains.

#define BM 128
#define BN 256
#define BK 128                          // int8 k per tile (128 bytes/row)
#define KTILES 48
#define STAGES 3
#define A_STAGE_BYTES (BM * 128)        // 16384
#define B_STAGE_BYTES (BN * 128)        // 32768
#define STAGE_BYTES (A_STAGE_BYTES + B_STAGE_BYTES)
#define SMEM_DYN (STAGES * STAGE_BYTES)

static __device__ __align__(16) int8_t g_Aq[4096ull * 4096];  // [m][A1(2048)|A2(2048)]
static __device__ __align__(16) int8_t g_Bq[4096ull * 4096];  // [n=g*1024+c][B1|B2]
static __device__ float g_sa[4096];      // sa_m (raw max)
static __device__ float g_sb[4096];      // sb_n * 128 / 16256^2
static __device__ float g_pre[4ull * 4096ull * 1024ull];

// ---------------- PTX helpers (baseline sm_80 ISA) ----------------
__device__ __forceinline__ uint32_t smem_u32(const void* p) {
    return (uint32_t)__cvta_generic_to_shared(p);
}
__device__ __forceinline__ void cp16(uint32_t dst, const void* src) {
    asm volatile("cp.async.cg.shared.global [%0], [%1], 16;\n" :: "r"(dst), "l"(src));
}
__device__ __forceinline__ void cp_commit() {
    asm volatile("cp.async.commit_group;\n" ::: "memory");
}
#define CP_WAIT(N) asm volatile("cp.async.wait_group %0;\n" :: "n"(N) : "memory")

__device__ __forceinline__ void ldsm_x4(uint32_t* r, uint32_t addr) {
    asm volatile("ldmatrix.sync.aligned.m8n8.x4.shared.b16 {%0,%1,%2,%3}, [%4];\n"
                 : "=r"(r[0]), "=r"(r[1]), "=r"(r[2]), "=r"(r[3]) : "r"(addr));
}
__device__ __forceinline__ void imma16832(int* c, const uint32_t* a,
                                          uint32_t b0, uint32_t b1) {
    asm volatile(
        "mma.sync.aligned.m16n8k32.row.col.s32.s8.s8.s32 "
        "{%0,%1,%2,%3}, {%4,%5,%6,%7}, {%8,%9}, {%0,%1,%2,%3};\n"
        : "+r"(c[0]), "+r"(c[1]), "+r"(c[2]), "+r"(c[3])
        : "r"(a[0]), "r"(a[1]), "r"(a[2]), "r"(a[3]), "r"(b0), "r"(b1));
}

// ---------------- quantization ----------------
__global__ __launch_bounds__(256)
void quant_hx(const float* __restrict__ x, const float* __restrict__ h) {
    __shared__ float sred[256];
    const int m = blockIdx.x;
    const int t = threadIdx.x;
    const float* src = (t < 128) ? (x + (size_t)m * 1024 + t * 8)
                                 : (h + (size_t)m * 1024 + (t - 128) * 8);
    float4 v0 = *(const float4*)src;
    float4 v1 = *(const float4*)(src + 4);
    float vals[8] = {v0.x, v0.y, v0.z, v0.w, v1.x, v1.y, v1.z, v1.w};
    float mx = 0.0f;
    #pragma unroll
    for (int j = 0; j < 8; ++j) mx = fmaxf(mx, fabsf(vals[j]));
    sred[t] = mx;
    __syncthreads();
    for (int s = 128; s > 0; s >>= 1) {
        if (t < s) sred[t] = fmaxf(sred[t], sred[t + s]);
        __syncthreads();
    }
    const float sa = fmaxf(sred[0], 1e-30f);
    if (t == 0) g_sa[m] = sa;
    const float inv = 16256.0f / sa;
    char d1[8], d2[8];
    #pragma unroll
    for (int j = 0; j < 8; ++j) {
        int vi = __float2int_rn(vals[j] * inv);
        int b1 = (vi + 64) >> 7;
        int b2 = vi - (b1 << 7);
        d1[j] = (char)b1;
        d2[j] = (char)b2;
    }
    size_t base = (size_t)m * 4096 + t * 8;
    *(uint2*)&g_Aq[base]        = *(uint2*)d1;
    *(uint2*)&g_Aq[base + 2048] = *(uint2*)d2;
}

__global__ __launch_bounds__(256)
void quant_w(const float* __restrict__ Wf, const float* __restrict__ Wi,
             const float* __restrict__ Ws, const float* __restrict__ Wp) {
    __shared__ float red[8][32];
    __shared__ float smax[32];
    __shared__ __align__(8) char t1[32][64];
    __shared__ __align__(8) char t2[32][64];

    const int g = blockIdx.y;
    const float* __restrict__ W = (g == 0) ? Wf : (g == 1) ? Wi : (g == 2) ? Ws : Wp;
    const int n0 = blockIdx.x * 32;
    const int tx = threadIdx.x & 31;
    const int tk = threadIdx.x >> 5;   // 0..7

    float mx = 0.0f;
    for (int k = tk; k < 2048; k += 8)
        mx = fmaxf(mx, fabsf(W[(size_t)k * 1024 + n0 + tx]));
    red[tk][tx] = mx;
    __syncthreads();
    if (tk == 0) {
        float m = red[0][tx];
        #pragma unroll
        for (int j = 1; j < 8; ++j) m = fmaxf(m, red[j][tx]);
        m = fmaxf(m, 1e-30f);
        smax[tx] = m;
        g_sb[g * 1024 + n0 + tx] = m * (128.0f / (16256.0f * 16256.0f));
    }
    __syncthreads();
    const float inv = 16256.0f / smax[tx];

    for (int kt = 0; kt < 2048; kt += 64) {
        #pragma unroll
        for (int j = 0; j < 8; ++j) {
            int k = kt + tk * 8 + j;
            float v = W[(size_t)k * 1024 + n0 + tx] * inv;
            int vi = __float2int_rn(v);
            int b1 = (vi + 64) >> 7;
            int b2 = vi - (b1 << 7);
            t1[tx][tk * 8 + j] = (char)b1;
            t2[tx][tk * 8 + j] = (char)b2;
        }
        __syncthreads();
        const int r = threadIdx.x >> 3, seg = threadIdx.x & 7;
        size_t row = (size_t)(g * 1024 + n0 + r) * 4096;
        *(uint2*)&g_Bq[row + kt + seg * 8]        = *(uint2*)&t1[r][seg * 8];
        *(uint2*)&g_Bq[row + 2048 + kt + seg * 8] = *(uint2*)&t2[r][seg * 8];
        __syncthreads();
    }
}

// ---------------- IMMA GEMM ----------------
__device__ __forceinline__ void koffs(int kt, int& ka, int& kb) {
    if (kt < 16)      { ka = kt << 7;                 kb = kt << 7; }
    else if (kt < 32) { ka = 2048 + ((kt - 16) << 7); kb = (kt - 16) << 7; }
    else              { ka = (kt - 32) << 7;          kb = 2048 + ((kt - 32) << 7); }
}

__device__ __forceinline__ void load_stage(uint32_t sbase, int stage, int m0, int n0,
                                           int tid) {
    const uint32_t sb = sbase + (uint32_t)(stage % STAGES) * STAGE_BYTES;
    int ka, kb;
    koffs(stage, ka, kb);
    #pragma unroll
    for (int j = 0; j < 4; ++j) {              // A: 128 rows x 128B
        int id = j * 256 + tid;
        int r = id >> 3, c = id & 7;
        uint32_t dst = sb + (uint32_t)(r * 128 + ((c ^ (r & 7)) * 16));
        cp16(dst, g_Aq + ((size_t)(m0 + r) * 4096 + ka + c * 16));
    }
    #pragma unroll
    for (int j = 0; j < 8; ++j) {              // B: 256 rows x 128B
        int id = j * 256 + tid;
        int r = id >> 3, c = id & 7;
        uint32_t dst = sb + (uint32_t)A_STAGE_BYTES
                     + (uint32_t)(r * 128 + ((c ^ (r & 7)) * 16));
        cp16(dst, g_Bq + ((size_t)(n0 + r) * 4096 + kb + c * 16));
    }
}

__global__ __launch_bounds__(256, 1)
void gemm_imma() {
    extern __shared__ char dyn[];
    const uint32_t sbase = smem_u32(dyn);

    const int tid = threadIdx.x;
    const int wid = tid >> 5;
    const int lane = tid & 31;
    const int warp_m = wid & 1;
    const int warp_n = wid >> 1;
    const int m0 = blockIdx.y * BM;
    const int n0 = blockIdx.x * BN;

    const int lrow = lane & 15;
    const int lhi  = lane >> 4;

    int acc[4][8][4];
    #pragma unroll
    for (int mi = 0; mi < 4; ++mi)
        #pragma unroll
        for (int nj = 0; nj < 8; ++nj)
            #pragma unroll
            for (int q = 0; q < 4; ++q) acc[mi][nj][q] = 0;

    load_stage(sbase, 0, m0, n0, tid); cp_commit();
    load_stage(sbase, 1, m0, n0, tid); cp_commit();

    for (int kt = 0; kt < KTILES; ++kt) {
        CP_WAIT(1);
        __syncthreads();

        if (kt + 2 < KTILES) load_stage(sbase, kt + 2, m0, n0, tid);
        cp_commit();

        if (kt == 16) {                 // acc = 128*G1; continue with cross terms
            #pragma unroll
            for (int mi = 0; mi < 4; ++mi)
                #pragma unroll
                for (int nj = 0; nj < 8; ++nj)
                    #pragma unroll
                    for (int q = 0; q < 4; ++q) acc[mi][nj][q] <<= 7;
        }

        const uint32_t sA = sbase + (uint32_t)(kt % STAGES) * STAGE_BYTES;
        const uint32_t sB = sA + A_STAGE_BYTES;

        #pragma unroll
        for (int ks = 0; ks < 4; ++ks) {       // 4 x k32 per 128B stage
            const int kc = ks * 2 + lhi;       // 16B chunk 0..7
            uint32_t a[4][4], b[4][4];
            #pragma unroll
            for (int mi = 0; mi < 4; ++mi) {
                int r = warp_m * 64 + mi * 16 + lrow;
                uint32_t addr = sA + (uint32_t)(r * 128 + ((kc ^ (r & 7)) * 16));
                ldsm_x4(a[mi], addr);
            }
            #pragma unroll
            for (int nj = 0; nj < 4; ++nj) {
                int r = warp_n * 64 + nj * 16 + lrow;
                uint32_t addr = sB + (uint32_t)(r * 128 + ((kc ^ (r & 7)) * 16));
                ldsm_x4(b[nj], addr);
            }
            #pragma unroll
            for (int mi = 0; mi < 4; ++mi)
                #pragma unroll
                for (int nj = 0; nj < 4; ++nj) {
                    imma16832(acc[mi][2 * nj],     a[mi], b[nj][0], b[nj][2]);
                    imma16832(acc[mi][2 * nj + 1], a[mi], b[nj][1], b[nj][3]);
                }
        }
    }

    // Epilogue: pre = g_sa[row] * g_sb[n] * acc
    const int gid = lane >> 2, tig = lane & 3;
    const int ngb = n0 + warp_n * 64;          // global col 0..4095
    const int gate = ngb >> 10;
    const int col0 = ngb & 1023;
    float* __restrict__ outg = g_pre + (size_t)gate * (4096ull * 1024ull);
    #pragma unroll
    for (int mi = 0; mi < 4; ++mi) {
        int row = m0 + warp_m * 64 + mi * 16 + gid;
        float s0 = g_sa[row];
        float s1 = g_sa[row + 8];
        float* p0 = outg + (size_t)row * 1024 + col0;
        float* p1 = p0 + 8ull * 1024ull;
        #pragma unroll
        for (int nj = 0; nj < 8; ++nj) {
            int col = nj * 8 + tig * 2;
            float2 sb2 = *(const float2*)&g_sb[ngb + col];
            *(float2*)(p0 + col) = make_float2(s0 * sb2.x * (float)acc[mi][nj][0],
                                               s0 * sb2.y * (float)acc[mi][nj][1]);
            *(float2*)(p1 + col) = make_float2(s1 * sb2.x * (float)acc[mi][nj][2],
                                               s1 * sb2.y * (float)acc[mi][nj][3]);
        }
    }
}

// ---------------- fused eltwise ----------------
__device__ __forceinline__ float sigf(float z) { return 1.0f / (1.0f + expf(-z)); }

__global__ __launch_bounds__(256)
void lstm_eltwise_kernel(const float* __restrict__ c,
                         const float* __restrict__ bf, const float* __restrict__ bi,
                         const float* __restrict__ bs, const float* __restrict__ bp,
                         float* __restrict__ out) {
    const size_t G = 4096ull * 1024ull;
    const size_t i4 = (size_t)blockIdx.x * blockDim.x + threadIdx.x;
    const size_t idx = i4 * 4;
    const int col = (int)(idx & 1023);

    float4 pf = *(const float4*)&g_pre[idx];
    float4 pi = *(const float4*)&g_pre[G + idx];
    float4 ps = *(const float4*)&g_pre[2 * G + idx];
    float4 pp = *(const float4*)&g_pre[3 * G + idx];
    float4 vbf = *(const float4*)&bf[col];
    float4 vbi = *(const float4*)&bi[col];
    float4 vbs = *(const float4*)&bs[col];
    float4 vbp = *(const float4*)&bp[col];
    float4 vc  = *(const float4*)&c[idx];

    const float* pfv = (const float*)&pf;  const float* piv = (const float*)&pi;
    const float* psv = (const float*)&ps;  const float* ppv = (const float*)&pp;
    const float* bfv = (const float*)&vbf; const float* biv = (const float*)&vbi;
    const float* bsv = (const float*)&vbs; const float* bpv = (const float*)&vbp;
    const float* cv  = (const float*)&vc;

    float4 o; float* ov = (float*)&o;
    #pragma unroll
    for (int j = 0; j < 4; ++j) {
        float f = sigf(pfv[j] + bfv[j]);
        float i = sigf(piv[j] + biv[j]);
        float s = sigf(psv[j] + bsv[j]);
        float p = tanhf(ppv[j] + bpv[j]);
        float cn = cv[j] * f + i * p;
        ov[j] = tanhf(cn) * s;
    }
    *(float4*)&out[idx] = o;
}

// ---------------- launch ----------------
extern "C" void kernel_launch(void* const* d_in, const int* in_sizes, int n_in,
                              void* d_out, int out_size) {
    const float* x  = (const float*)d_in[0];
    const float* h  = (const float*)d_in[1];
    const float* c  = (const float*)d_in[2];
    const float* Wf = (const float*)d_in[3];
    const float* bf = (const float*)d_in[4];
    const float* Wi = (const float*)d_in[5];
    const float* bi = (const float*)d_in[6];
    const float* Ws = (const float*)d_in[7];
    const float* bs = (const float*)d_in[8];
    const float* Wp = (const float*)d_in[9];
    const float* bp = (const float*)d_in[10];
    float* out = (float*)d_out;

    cudaFuncSetAttribute(gemm_imma, cudaFuncAttributeMaxDynamicSharedMemorySize,
                         SMEM_DYN);

    quant_hx<<<4096, 256>>>(x, h);
    quant_w<<<dim3(32, 4), 256>>>(Wf, Wi, Ws, Wp);
    gemm_imma<<<dim3(4096 / BN, 4096 / BM), 256, SMEM_DYN>>>();
    lstm_eltwise_kernel<<<4096, 256>>>(c, bf, bi, bs, bp, out);
}